// round 12
// baseline (speedup 1.0000x reference)
#include <cuda_runtime.h>
#include <cstdint>

#define SEQ  4096
#define NQ   64
#define DH   128
#define BMAX 16
#define SCALE 0.088388347648318447f
#define P 136
#define TILE_U (32*P)
#define NCH (SEQ/32)
#define SM_AS (4*TILE_U)
#define SM_OP (SM_AS + SEQ)
#define SM_WP (SM_OP + 32*DH)
#define DSMEM ((SM_WP + 32*DH)*4)

__device__ float g_Kr[(size_t)BMAX*SEQ*DH];
__device__ float g_Vr[(size_t)BMAX*SEQ*DH];

__device__ __forceinline__ float tf32r(float x) {
    uint32_t r;
    asm("cvt.rna.tf32.f32 %0, %1;" : "=r"(r) : "f"(x));
    return __uint_as_float(r);
}
__device__ __forceinline__ void mma_tf32(float* d, const uint32_t* a,
                                         uint32_t b0, uint32_t b1) {
    asm volatile(
        "mma.sync.aligned.m16n8k8.row.col.f32.tf32.tf32.f32 "
        "{%0,%1,%2,%3}, {%4,%5,%6,%7}, {%8,%9}, {%0,%1,%2,%3};"
        : "+f"(d[0]), "+f"(d[1]), "+f"(d[2]), "+f"(d[3])
        : "r"(a[0]), "r"(a[1]), "r"(a[2]), "r"(a[3]), "r"(b0), "r"(b1));
}
#define BAR_SYNC(id)   asm volatile("bar.sync %0, 512;"   :: "r"(id) : "memory")
#define BAR_ARRIVE(id) asm volatile("bar.arrive %0, 512;" :: "r"(id) : "memory")
#define MEMBAR_CTA()   asm volatile("membar.cta;" ::: "memory")

__global__ void prep_kernel(const float* __restrict__ K, const float* __restrict__ V,
                            int total4) {
    int i = blockIdx.x * blockDim.x + threadIdx.x;
    if (i >= total4) return;
    float4 k = ((const float4*)K)[i];
    float4 v = ((const float4*)V)[i];
    ((float4*)g_Kr)[i] = make_float4(tf32r(k.x), tf32r(k.y), tf32r(k.z), tf32r(k.w));
    ((float4*)g_Vr)[i] = make_float4(tf32r(v.x), tf32r(v.y), tf32r(v.z), tf32r(v.w));
}

__global__ __launch_bounds__(512, 1)
void jac_tc(const float* __restrict__ Q, const float* __restrict__ K,
            float* __restrict__ out)
{
    extern __shared__ uint32_t sm[];
    float* a_s   = (float*)(sm + SM_AS);
    float* opart = (float*)(sm + SM_OP);
    float* wpart = (float*)(sm + SM_WP);
    __shared__ float q_sm[DH], o_sm[DH], w_sm[DH], red_sm[16];

    const int tid = threadIdx.x, lane = tid & 31, wid = tid >> 5;
    const int q = blockIdx.x, b = blockIdx.y;
    const float* __restrict__ Kb = K + (size_t)b * SEQ * DH;

    if (tid < 32) ((float4*)q_sm)[tid] =
        ((const float4*)(Q + ((size_t)b*NQ + q)*DH))[tid];
    __syncthreads();

    // ---- Phase 1: scores ----
    float4 qf = ((const float4*)q_sm)[lane];
    float lmax = -1e30f;
    for (int n = wid; n < SEQ; n += 16) {
        float4 kf = ((const float4*)(Kb + (size_t)n*DH))[lane];
        float dp = qf.x*kf.x + qf.y*kf.y + qf.z*kf.z + qf.w*kf.w;
        dp += __shfl_xor_sync(~0u, dp, 16); dp += __shfl_xor_sync(~0u, dp, 8);
        dp += __shfl_xor_sync(~0u, dp, 4);  dp += __shfl_xor_sync(~0u, dp, 2);
        dp += __shfl_xor_sync(~0u, dp, 1);
        dp *= SCALE;
        if (lane == 0) a_s[n] = dp;
        lmax = fmaxf(lmax, dp);
    }
    if (lane == 0) red_sm[wid] = lmax;
    __syncthreads();
    float gmax = red_sm[0];
    #pragma unroll
    for (int i = 1; i < 16; i++) gmax = fmaxf(gmax, red_sm[i]);
    __syncthreads();

    // ---- Phase 2: softmax ----
    float lsum = 0.f;
    for (int n = tid; n < SEQ; n += 512) {
        float e = __expf(a_s[n] - gmax); a_s[n] = e; lsum += e;
    }
    lsum += __shfl_xor_sync(~0u, lsum, 16); lsum += __shfl_xor_sync(~0u, lsum, 8);
    lsum += __shfl_xor_sync(~0u, lsum, 4);  lsum += __shfl_xor_sync(~0u, lsum, 2);
    lsum += __shfl_xor_sync(~0u, lsum, 1);
    if (lane == 0) red_sm[wid] = lsum;
    __syncthreads();
    float gsum = 0.f;
    #pragma unroll
    for (int i = 0; i < 16; i++) gsum += red_sm[i];
    const float inv = 1.0f / gsum;
    for (int n = tid; n < SEQ; n += 512) a_s[n] *= inv;
    __syncthreads();

    // ---- Phase 3: warp-specialized producer/consumer ----
    const float* Krb = g_Kr + (size_t)b*SEQ*DH;
    const float* Vrb = g_Vr + (size_t)b*SEQ*DH;

    if (wid < 8) {
        // ================= PRODUCER (256 threads) =================
        const int row = tid >> 3;          // 0..31
        const int cb  = (tid & 7) * 16;    // 16-col slice
        float pov[16], pwv[16];
        #pragma unroll
        for (int j = 0; j < 16; j++) { pov[j] = 0.f; pwv[j] = 0.f; }
        float4 KA[4], VA[4], KB[4], VB[4];

        #define LDCH(Kd, Vd, c_) do {                                        \
            const float4* _ks = (const float4*)(Krb + (size_t)((c_)*32+row)*DH + cb); \
            const float4* _vs = (const float4*)(Vrb + (size_t)((c_)*32+row)*DH + cb); \
            _Pragma("unroll")                                                \
            for (int _j = 0; _j < 4; _j++) { Kd[_j]=_ks[_j]; Vd[_j]=_vs[_j]; } \
        } while (0)

        #define STAGE(Kr_, Vr_, bsel_, ch_) do {                             \
            uint32_t* _kd = sm + (bsel_)*TILE_U      + row*P + cb;           \
            uint32_t* _wd = sm + (2+(bsel_))*TILE_U  + row*P + cb;           \
            float _av = a_s[(ch_)*32 + row];                                 \
            _Pragma("unroll")                                                \
            for (int _j = 0; _j < 4; _j++) {                                 \
                float4 _kv = Kr_[_j];                                        \
                pwv[4*_j  ] += _av*_kv.x;  pwv[4*_j+1] += _av*_kv.y;         \
                pwv[4*_j+2] += _av*_kv.z;  pwv[4*_j+3] += _av*_kv.w;         \
                *(float4*)(_kd + 4*_j) = _kv;                                \
                float4 _vv = Vr_[_j];                                        \
                float4 _wv = make_float4(_av*_vv.x,_av*_vv.y,_av*_vv.z,_av*_vv.w); \
                pov[4*_j  ] += _wv.x;  pov[4*_j+1] += _wv.y;                 \
                pov[4*_j+2] += _wv.z;  pov[4*_j+3] += _wv.w;                 \
                *(uint4*)(_wd + 4*_j) = make_uint4(                          \
                    __float_as_uint(_wv.x)+0x1000u, __float_as_uint(_wv.y)+0x1000u, \
                    __float_as_uint(_wv.z)+0x1000u, __float_as_uint(_wv.w)+0x1000u);\
            }                                                                \
        } while (0)

        LDCH(KA, VA, 0);
        for (int ch = 0; ch < NCH; ch += 2) {
            if (ch >= 2) BAR_SYNC(3);
            STAGE(KA, VA, 0, ch);
            MEMBAR_CTA(); BAR_ARRIVE(1);
            LDCH(KB, VB, ch + 1);
            if (ch >= 2) BAR_SYNC(4);
            STAGE(KB, VB, 1, ch + 1);
            MEMBAR_CTA(); BAR_ARRIVE(2);
            int nx = (ch + 2 < NCH) ? ch + 2 : NCH - 1;
            LDCH(KA, VA, nx);
        }
        #pragma unroll
        for (int j = 0; j < 16; j++) {
            opart[row*DH + cb + j] = pov[j];
            wpart[row*DH + cb + j] = pwv[j];
        }
    } else {
        // ================= CONSUMER (256 threads) =================
        const int cwid = wid - 8;
        const int g = lane >> 2, ti = lane & 3;
        const int v0 = (cwid & 1) * 64, k0 = (cwid >> 1) * 32;
        float acc[4][4][4];
        #pragma unroll
        for (int mi = 0; mi < 4; mi++)
            #pragma unroll
            for (int nj = 0; nj < 4; nj++)
                #pragma unroll
                for (int e = 0; e < 4; e++) acc[mi][nj][e] = 0.f;

        for (int ch = 0; ch < NCH; ch++) {
            const int bsel = ch & 1;
            BAR_SYNC(1 + bsel);
            const uint32_t* Kc = sm + bsel*TILE_U;
            const uint32_t* Wc = sm + (2+bsel)*TILE_U;
            #pragma unroll
            for (int s = 0; s < 4; s++) {
                const uint32_t* Wr0 = Wc + (s*8 + ti)*P;
                const uint32_t* Wr4 = Wr0 + 4*P;
                uint32_t af[4][4];
                #pragma unroll
                for (int mi = 0; mi < 4; mi++) {
                    int cbv = v0 + mi*16 + g;
                    af[mi][0] = Wr0[cbv];   af[mi][1] = Wr0[cbv+8];
                    af[mi][2] = Wr4[cbv];   af[mi][3] = Wr4[cbv+8];
                }
                const uint32_t* Kr0 = Kc + (s*8 + ti)*P;
                const uint32_t* Kr4 = Kr0 + 4*P;
                #pragma unroll
                for (int nj = 0; nj < 4; nj++) {
                    int cbk = k0 + nj*8 + g;
                    uint32_t b0 = Kr0[cbk], b1 = Kr4[cbk];
                    #pragma unroll
                    for (int mi = 0; mi < 4; mi++)
                        mma_tf32(acc[mi][nj], af[mi], b0, b1);
                }
            }
            BAR_ARRIVE(3 + bsel);
        }

        // park accs; wait for reductions below, then write out
        __syncthreads();     // join producers (they hit the matching one below)
        // (reduction done by low tids = producers; consumers pass through)
        __syncthreads();

        float* ob = out + ((size_t)b*NQ + q) * DH * DH;
        #pragma unroll
        for (int mi = 0; mi < 4; mi++) {
            int vr = v0 + mi*16 + g;
            float ov1 = o_sm[vr], ov2 = o_sm[vr + 8];
            #pragma unroll
            for (int nj = 0; nj < 4; nj++) {
                int kc = k0 + nj*8 + ti*2;
                float w1 = w_sm[kc], w2 = w_sm[kc+1];
                float2 r1 = make_float2(SCALE*(acc[mi][nj][0] - ov1*w1),
                                        SCALE*(acc[mi][nj][1] - ov1*w2));
                float2 r2 = make_float2(SCALE*(acc[mi][nj][2] - ov2*w1),
                                        SCALE*(acc[mi][nj][3] - ov2*w2));
                *(float2*)(ob + (size_t)vr*DH + kc)     = r1;
                *(float2*)(ob + (size_t)(vr+8)*DH + kc) = r2;
            }
        }
        return;
    }

    // producers: reductions between the two joint barriers
    __syncthreads();
    if (tid < DH) {
        float s = 0.f;
        #pragma unroll
        for (int n = 0; n < 32; n++) s += opart[n*DH + tid];
        o_sm[tid] = s;
    } else if (tid < 2*DH) {
        int t = tid - DH;
        float s = 0.f;
        #pragma unroll
        for (int n = 0; n < 32; n++) s += wpart[n*DH + t];
        w_sm[t] = s;
    }
    __syncthreads();
}

extern "C" void kernel_launch(void* const* d_in, const int* in_sizes, int n_in,
                              void* d_out, int out_size) {
    const float* Q = (const float*)d_in[0];
    const float* K = (const float*)d_in[1];
    const float* V = (const float*)d_in[2];
    float* out = (float*)d_out;
    int batch = in_sizes[1] / (SEQ * DH);
    int total4 = batch * SEQ * DH / 4;
    prep_kernel<<<(total4 + 255)/256, 256>>>(K, V, total4);
    cudaFuncSetAttribute(jac_tc, cudaFuncAttributeMaxDynamicSharedMemorySize, DSMEM);
    jac_tc<<<dim3(NQ, batch), 512, DSMEM>>>(Q, K, out);
}

// round 13
// speedup vs baseline: 1.4046x; 1.4046x over previous
#include <cuda_runtime.h>
#include <cstdint>

#define SEQ  4096
#define NQ   64
#define DH   128
#define BMAX 16
#define SCALE 0.088388347648318447f
#define P 136
#define TILE_U (32*P)
#define NCH (SEQ/32)
// K tiles x2, W tiles x2, a_s
#define DSMEM ((4*TILE_U + SEQ)*4)

__device__ float g_Kr[(size_t)BMAX*SEQ*DH];
__device__ float g_Vr[(size_t)BMAX*SEQ*DH];

__device__ __forceinline__ float tf32r(float x) {
    uint32_t r;
    asm("cvt.rna.tf32.f32 %0, %1;" : "=r"(r) : "f"(x));
    return __uint_as_float(r);
}
__device__ __forceinline__ void mma_tf32(float* d, const uint32_t* a,
                                         uint32_t b0, uint32_t b1) {
    asm volatile(
        "mma.sync.aligned.m16n8k8.row.col.f32.tf32.tf32.f32 "
        "{%0,%1,%2,%3}, {%4,%5,%6,%7}, {%8,%9}, {%0,%1,%2,%3};"
        : "+f"(d[0]), "+f"(d[1]), "+f"(d[2]), "+f"(d[3])
        : "r"(a[0]), "r"(a[1]), "r"(a[2]), "r"(a[3]), "r"(b0), "r"(b1));
}

__global__ void prep_kernel(const float* __restrict__ K, const float* __restrict__ V,
                            int total4) {
    int i = blockIdx.x * blockDim.x + threadIdx.x;
    if (i >= total4) return;
    float4 k = ((const float4*)K)[i];
    float4 v = ((const float4*)V)[i];
    ((float4*)g_Kr)[i] = make_float4(tf32r(k.x), tf32r(k.y), tf32r(k.z), tf32r(k.w));
    ((float4*)g_Vr)[i] = make_float4(tf32r(v.x), tf32r(v.y), tf32r(v.z), tf32r(v.w));
}

__global__ __launch_bounds__(256, 2)
void jac_tc(const float* __restrict__ Q, const float* __restrict__ K,
            float* __restrict__ out)
{
    extern __shared__ uint32_t sm[];
    float* a_s = (float*)(sm + 4*TILE_U);
    __shared__ float q_sm[DH], o_sm[DH], w_sm[DH], red_sm[8];

    const int tid = threadIdx.x, lane = tid & 31, wid = tid >> 5;
    const int q = blockIdx.x, b = blockIdx.y;
    const float* __restrict__ Kb = K + (size_t)b * SEQ * DH;

    if (tid < 32) ((float4*)q_sm)[tid] =
        ((const float4*)(Q + ((size_t)b*NQ + q)*DH))[tid];
    __syncthreads();

    // ---- Phase 1: scores ----
    float4 qf = ((const float4*)q_sm)[lane];
    float lmax = -1e30f;
    for (int n = wid; n < SEQ; n += 8) {
        float4 kf = ((const float4*)(Kb + (size_t)n*DH))[lane];
        float dp = qf.x*kf.x + qf.y*kf.y + qf.z*kf.z + qf.w*kf.w;
        dp += __shfl_xor_sync(~0u, dp, 16); dp += __shfl_xor_sync(~0u, dp, 8);
        dp += __shfl_xor_sync(~0u, dp, 4);  dp += __shfl_xor_sync(~0u, dp, 2);
        dp += __shfl_xor_sync(~0u, dp, 1);
        dp *= SCALE;
        if (lane == 0) a_s[n] = dp;
        lmax = fmaxf(lmax, dp);
    }
    if (lane == 0) red_sm[wid] = lmax;
    __syncthreads();
    float gmax = red_sm[0];
    #pragma unroll
    for (int i = 1; i < 8; i++) gmax = fmaxf(gmax, red_sm[i]);
    __syncthreads();

    // ---- Phase 2: softmax ----
    float lsum = 0.f;
    for (int n = tid; n < SEQ; n += 256) {
        float e = __expf(a_s[n] - gmax); a_s[n] = e; lsum += e;
    }
    lsum += __shfl_xor_sync(~0u, lsum, 16); lsum += __shfl_xor_sync(~0u, lsum, 8);
    lsum += __shfl_xor_sync(~0u, lsum, 4);  lsum += __shfl_xor_sync(~0u, lsum, 2);
    lsum += __shfl_xor_sync(~0u, lsum, 1);
    if (lane == 0) red_sm[wid] = lsum;
    __syncthreads();
    float gsum = 0.f;
    #pragma unroll
    for (int i = 0; i < 8; i++) gsum += red_sm[i];
    const float inv = 1.0f / gsum;
    for (int n = tid; n < SEQ; n += 256) a_s[n] *= inv;
    __syncthreads();

    // ---- Phase 3: bulk-sync tf32 mma, 2 CTAs/SM overlap ----
    const float* Krb = g_Kr + (size_t)b*SEQ*DH;
    const float* Vrb = g_Vr + (size_t)b*SEQ*DH;
    const int sn = tid >> 4, sc = (tid & 15) * 8;   // rows sn, sn+16; 8 cols
    const int g = lane >> 2, ti = lane & 3;
    const int v0 = (wid & 1) * 64, k0 = (wid >> 1) * 32;

    float pov[8], pwv[8];
    #pragma unroll
    for (int j = 0; j < 8; j++) { pov[j] = 0.f; pwv[j] = 0.f; }
    float acc[4][4][4];
    #pragma unroll
    for (int mi = 0; mi < 4; mi++)
        #pragma unroll
        for (int nj = 0; nj < 4; nj++)
            #pragma unroll
            for (int e = 0; e < 4; e++) acc[mi][nj][e] = 0.f;

    for (int ch = 0; ch < NCH; ch++) {
        const int n0 = ch * 32, bsel = ch & 1;
        uint32_t* Kc = sm + bsel*TILE_U;
        uint32_t* Wc = sm + (2+bsel)*TILE_U;
        {   // stage rows sn and sn+16
            const float a0 = a_s[n0 + sn];
            const float a1 = a_s[n0 + sn + 16];
            const float4* kr0 = (const float4*)(Krb + (size_t)(n0+sn)*DH + sc);
            const float4* kr1 = (const float4*)(Krb + (size_t)(n0+sn+16)*DH + sc);
            const float4* vr0 = (const float4*)(Vrb + (size_t)(n0+sn)*DH + sc);
            const float4* vr1 = (const float4*)(Vrb + (size_t)(n0+sn+16)*DH + sc);
            uint32_t* kd0 = Kc + sn*P + sc;  uint32_t* kd1 = kd0 + 16*P;
            uint32_t* wd0 = Wc + sn*P + sc;  uint32_t* wd1 = wd0 + 16*P;
            #pragma unroll
            for (int j = 0; j < 2; j++) {
                float4 ka = kr0[j], kb = kr1[j];
                pwv[4*j  ] += a0*ka.x + a1*kb.x;
                pwv[4*j+1] += a0*ka.y + a1*kb.y;
                pwv[4*j+2] += a0*ka.z + a1*kb.z;
                pwv[4*j+3] += a0*ka.w + a1*kb.w;
                *(float4*)(kd0 + 4*j) = ka;
                *(float4*)(kd1 + 4*j) = kb;
                float4 va = vr0[j], vb = vr1[j];
                float4 w0 = make_float4(a0*va.x, a0*va.y, a0*va.z, a0*va.w);
                float4 w1 = make_float4(a1*vb.x, a1*vb.y, a1*vb.z, a1*vb.w);
                pov[4*j  ] += w0.x + w1.x;  pov[4*j+1] += w0.y + w1.y;
                pov[4*j+2] += w0.z + w1.z;  pov[4*j+3] += w0.w + w1.w;
                *(uint4*)(wd0 + 4*j) = make_uint4(
                    __float_as_uint(w0.x)+0x1000u, __float_as_uint(w0.y)+0x1000u,
                    __float_as_uint(w0.z)+0x1000u, __float_as_uint(w0.w)+0x1000u);
                *(uint4*)(wd1 + 4*j) = make_uint4(
                    __float_as_uint(w1.x)+0x1000u, __float_as_uint(w1.y)+0x1000u,
                    __float_as_uint(w1.z)+0x1000u, __float_as_uint(w1.w)+0x1000u);
            }
        }
        __syncthreads();
        // mma: 8 warps, 64x32 tiles (mapping HW-verified in R12)
        #pragma unroll
        for (int s = 0; s < 4; s++) {
            const uint32_t* Wr0 = Wc + (s*8 + ti)*P;
            const uint32_t* Wr4 = Wr0 + 4*P;
            uint32_t af[4][4];
            #pragma unroll
            for (int mi = 0; mi < 4; mi++) {
                int cbv = v0 + mi*16 + g;
                af[mi][0] = Wr0[cbv];   af[mi][1] = Wr0[cbv+8];
                af[mi][2] = Wr4[cbv];   af[mi][3] = Wr4[cbv+8];
            }
            const uint32_t* Kr0 = Kc + (s*8 + ti)*P;
            const uint32_t* Kr4 = Kr0 + 4*P;
            #pragma unroll
            for (int nj = 0; nj < 4; nj++) {
                int cbk = k0 + nj*8 + g;
                uint32_t b0 = Kr0[cbk], b1 = Kr4[cbk];
                #pragma unroll
                for (int mi = 0; mi < 4; mi++)
                    mma_tf32(acc[mi][nj], af[mi], b0, b1);
            }
        }
    }
    __syncthreads();

    // ---- reduce o/w partials (reuse tile smem; 16 rows) ----
    float* opart = (float*)sm;               // [16][128]
    float* wpart = (float*)(sm + TILE_U);    // [16][128]
    #pragma unroll
    for (int j = 0; j < 8; j++) {
        opart[sn*DH + sc + j] = pov[j];
        wpart[sn*DH + sc + j] = pwv[j];
    }
    __syncthreads();
    if (tid < DH) {
        float s = 0.f;
        #pragma unroll
        for (int n = 0; n < 16; n++) s += opart[n*DH + tid];
        o_sm[tid] = s;
    } else {
        int t = tid - DH;
        float s = 0.f;
        #pragma unroll
        for (int n = 0; n < 16; n++) s += wpart[n*DH + t];
        w_sm[t] = s;
    }
    __syncthreads();

    // ---- epilogue (mapping HW-verified in R12) ----
    float* ob = out + ((size_t)b*NQ + q) * DH * DH;
    #pragma unroll
    for (int mi = 0; mi < 4; mi++) {
        int vr = v0 + mi*16 + g;
        float ov1 = o_sm[vr], ov2 = o_sm[vr + 8];
        #pragma unroll
        for (int nj = 0; nj < 4; nj++) {
            int kc = k0 + nj*8 + ti*2;
            float w1 = w_sm[kc], w2 = w_sm[kc+1];
            float2 r1 = make_float2(SCALE*(acc[mi][nj][0] - ov1*w1),
                                    SCALE*(acc[mi][nj][1] - ov1*w2));
            float2 r2 = make_float2(SCALE*(acc[mi][nj][2] - ov2*w1),
                                    SCALE*(acc[mi][nj][3] - ov2*w2));
            *(float2*)(ob + (size_t)vr*DH + kc)     = r1;
            *(float2*)(ob + (size_t)(vr+8)*DH + kc) = r2;
        }
    }
}

extern "C" void kernel_launch(void* const* d_in, const int* in_sizes, int n_in,
                              void* d_out, int out_size) {
    const float* Q = (const float*)d_in[0];
    const float* K = (const float*)d_in[1];
    const float* V = (const float*)d_in[2];
    float* out = (float*)d_out;
    int batch = in_sizes[1] / (SEQ * DH);
    int total4 = batch * SEQ * DH / 4;
    prep_kernel<<<(total4 + 255)/256, 256>>>(K, V, total4);
    cudaFuncSetAttribute(jac_tc, cudaFuncAttributeMaxDynamicSharedMemorySize, DSMEM);
    jac_tc<<<dim3(NQ, batch), 256, DSMEM>>>(Q, K, out);
}

// round 14
// speedup vs baseline: 1.4199x; 1.0109x over previous
#include <cuda_runtime.h>
#include <cstdint>

#define SEQ  4096
#define NQ   64
#define DH   128
#define BMAX 16
#define SCALE 0.088388347648318447f
#define P 136
#define TILE_U (32*P)
#define NCH (SEQ/32)
#define DSMEM ((4*TILE_U + SEQ)*4)

__device__ float g_Kr[(size_t)BMAX*SEQ*DH];
__device__ float g_Vr[(size_t)BMAX*SEQ*DH];

__device__ __forceinline__ float tf32r(float x) {
    uint32_t r;
    asm("cvt.rna.tf32.f32 %0, %1;" : "=r"(r) : "f"(x));
    return __uint_as_float(r);
}
__device__ __forceinline__ void mma_tf32(float* d, const uint32_t* a,
                                         uint32_t b0, uint32_t b1) {
    asm volatile(
        "mma.sync.aligned.m16n8k8.row.col.f32.tf32.tf32.f32 "
        "{%0,%1,%2,%3}, {%4,%5,%6,%7}, {%8,%9}, {%0,%1,%2,%3};"
        : "+f"(d[0]), "+f"(d[1]), "+f"(d[2]), "+f"(d[3])
        : "r"(a[0]), "r"(a[1]), "r"(a[2]), "r"(a[3]), "r"(b0), "r"(b1));
}
__device__ __forceinline__ void cpa16(uint32_t dst, const void* src) {
    asm volatile("cp.async.ca.shared.global [%0], [%1], 16;" :: "r"(dst), "l"(src));
}
#define CPA_COMMIT() asm volatile("cp.async.commit_group;" ::: "memory")
#define CPA_WAIT0()  asm volatile("cp.async.wait_group 0;" ::: "memory")

__global__ void prep_kernel(const float* __restrict__ K, const float* __restrict__ V,
                            int total4) {
    int i = blockIdx.x * blockDim.x + threadIdx.x;
    if (i >= total4) return;
    float4 k = ((const float4*)K)[i];
    float4 v = ((const float4*)V)[i];
    ((float4*)g_Kr)[i] = make_float4(tf32r(k.x), tf32r(k.y), tf32r(k.z), tf32r(k.w));
    ((float4*)g_Vr)[i] = make_float4(tf32r(v.x), tf32r(v.y), tf32r(v.z), tf32r(v.w));
}

__global__ __launch_bounds__(256, 2)
void jac_tc(const float* __restrict__ Q, const float* __restrict__ K,
            float* __restrict__ out)
{
    extern __shared__ uint32_t sm[];
    float* a_s = (float*)(sm + 4*TILE_U);
    __shared__ float q_sm[DH], o_sm[DH], w_sm[DH], red_sm[8];

    const int tid = threadIdx.x, lane = tid & 31, wid = tid >> 5;
    const int q = blockIdx.x, b = blockIdx.y;
    const float* __restrict__ Kb = K + (size_t)b * SEQ * DH;

    if (tid < 32) ((float4*)q_sm)[tid] =
        ((const float4*)(Q + ((size_t)b*NQ + q)*DH))[tid];
    __syncthreads();

    // ---- Phase 1: scores ----
    float4 qf = ((const float4*)q_sm)[lane];
    float lmax = -1e30f;
    for (int n = wid; n < SEQ; n += 8) {
        float4 kf = ((const float4*)(Kb + (size_t)n*DH))[lane];
        float dp = qf.x*kf.x + qf.y*kf.y + qf.z*kf.z + qf.w*kf.w;
        dp += __shfl_xor_sync(~0u, dp, 16); dp += __shfl_xor_sync(~0u, dp, 8);
        dp += __shfl_xor_sync(~0u, dp, 4);  dp += __shfl_xor_sync(~0u, dp, 2);
        dp += __shfl_xor_sync(~0u, dp, 1);
        dp *= SCALE;
        if (lane == 0) a_s[n] = dp;
        lmax = fmaxf(lmax, dp);
    }
    if (lane == 0) red_sm[wid] = lmax;
    __syncthreads();
    float gmax = red_sm[0];
    #pragma unroll
    for (int i = 1; i < 8; i++) gmax = fmaxf(gmax, red_sm[i]);
    __syncthreads();

    // ---- Phase 2: softmax ----
    float lsum = 0.f;
    for (int n = tid; n < SEQ; n += 256) {
        float e = __expf(a_s[n] - gmax); a_s[n] = e; lsum += e;
    }
    lsum += __shfl_xor_sync(~0u, lsum, 16); lsum += __shfl_xor_sync(~0u, lsum, 8);
    lsum += __shfl_xor_sync(~0u, lsum, 4);  lsum += __shfl_xor_sync(~0u, lsum, 2);
    lsum += __shfl_xor_sync(~0u, lsum, 1);
    if (lane == 0) red_sm[wid] = lsum;
    __syncthreads();
    float gsum = 0.f;
    #pragma unroll
    for (int i = 0; i < 8; i++) gsum += red_sm[i];
    const float inv = 1.0f / gsum;
    for (int n = tid; n < SEQ; n += 256) a_s[n] *= inv;
    __syncthreads();

    // ---- Phase 3: chunk-pair batched tf32 mma ----
    const float* Krb = g_Kr + (size_t)b*SEQ*DH;
    const float* Vrb = g_Vr + (size_t)b*SEQ*DH;
    const int sn = tid >> 4, sc = (tid & 15) * 8;
    const int g = lane >> 2, ti = lane & 3;
    const int v0 = (wid & 1) * 64, k0 = (wid >> 1) * 32;
    const uint32_t ksa = (uint32_t)__cvta_generic_to_shared(sm);

    float pov[8], pwv[8];
    #pragma unroll
    for (int j = 0; j < 8; j++) { pov[j] = 0.f; pwv[j] = 0.f; }
    float acc[4][4][4];
    #pragma unroll
    for (int mi = 0; mi < 4; mi++)
        #pragma unroll
        for (int nj = 0; nj < 4; nj++)
            #pragma unroll
            for (int e = 0; e < 4; e++) acc[mi][nj][e] = 0.f;

    for (int ch = 0; ch < NCH; ch += 2) {
        const int n0 = ch * 32;
        // -- stage K (cp.async, both buffers) --
        #pragma unroll
        for (int u = 0; u < 2; u++) {
            const int nn = n0 + u*32;
            uint32_t kd = ksa + (uint32_t)(u*TILE_U + sn*P + sc) * 4;
            const float* ks0 = Krb + (size_t)(nn+sn)*DH + sc;
            const float* ks1 = Krb + (size_t)(nn+sn+16)*DH + sc;
            cpa16(kd, ks0);              cpa16(kd + 16, ks0 + 4);
            cpa16(kd + 16*P*4, ks1);     cpa16(kd + 16*P*4 + 16, ks1 + 4);
        }
        CPA_COMMIT();
        // -- stage W = a*V (both buffers) + o partials --
        #pragma unroll
        for (int u = 0; u < 2; u++) {
            const int nn = n0 + u*32;
            const float a0 = a_s[nn + sn];
            const float a1 = a_s[nn + sn + 16];
            const float4* vr0 = (const float4*)(Vrb + (size_t)(nn+sn)*DH + sc);
            const float4* vr1 = (const float4*)(Vrb + (size_t)(nn+sn+16)*DH + sc);
            uint32_t* wd0 = sm + (2+u)*TILE_U + sn*P + sc;
            uint32_t* wd1 = wd0 + 16*P;
            #pragma unroll
            for (int j = 0; j < 2; j++) {
                float4 va = vr0[j], vb = vr1[j];
                float4 w0 = make_float4(a0*va.x, a0*va.y, a0*va.z, a0*va.w);
                float4 w1 = make_float4(a1*vb.x, a1*vb.y, a1*vb.z, a1*vb.w);
                pov[4*j  ] += w0.x + w1.x;  pov[4*j+1] += w0.y + w1.y;
                pov[4*j+2] += w0.z + w1.z;  pov[4*j+3] += w0.w + w1.w;
                *(uint4*)(wd0 + 4*j) = make_uint4(
                    __float_as_uint(w0.x)+0x1000u, __float_as_uint(w0.y)+0x1000u,
                    __float_as_uint(w0.z)+0x1000u, __float_as_uint(w0.w)+0x1000u);
                *(uint4*)(wd1 + 4*j) = make_uint4(
                    __float_as_uint(w1.x)+0x1000u, __float_as_uint(w1.y)+0x1000u,
                    __float_as_uint(w1.z)+0x1000u, __float_as_uint(w1.w)+0x1000u);
            }
        }
        CPA_WAIT0();
        __syncthreads();
        // -- mma both buffers --
        #pragma unroll
        for (int u = 0; u < 2; u++) {
            const uint32_t* Kc = sm + u*TILE_U;
            const uint32_t* Wc = sm + (2+u)*TILE_U;
            #pragma unroll
            for (int s = 0; s < 4; s++) {
                const uint32_t* Wr0 = Wc + (s*8 + ti)*P;
                const uint32_t* Wr4 = Wr0 + 4*P;
                uint32_t af[4][4];
                #pragma unroll
                for (int mi = 0; mi < 4; mi++) {
                    int cbv = v0 + mi*16 + g;
                    af[mi][0] = Wr0[cbv];   af[mi][1] = Wr0[cbv+8];
                    af[mi][2] = Wr4[cbv];   af[mi][3] = Wr4[cbv+8];
                }
                const uint32_t* Kr0 = Kc + (s*8 + ti)*P;
                const uint32_t* Kr4 = Kr0 + 4*P;
                #pragma unroll
                for (int nj = 0; nj < 4; nj++) {
                    int cbk = k0 + nj*8 + g;
                    uint32_t b0 = Kr0[cbk], b1 = Kr4[cbk];
                    #pragma unroll
                    for (int mi = 0; mi < 4; mi++)
                        mma_tf32(acc[mi][nj], af[mi], b0, b1);
                }
            }
        }
        // -- w partials from resident K tiles --
        #pragma unroll
        for (int u = 0; u < 2; u++) {
            const int nn = n0 + u*32;
            const float a0 = a_s[nn + sn];
            const float a1 = a_s[nn + sn + 16];
            const uint32_t* Ks0 = sm + u*TILE_U + sn*P + sc;
            const uint32_t* Ks1 = Ks0 + 16*P;
            #pragma unroll
            for (int j = 0; j < 2; j++) {
                uint4 ka = *(const uint4*)(Ks0 + 4*j);
                uint4 kb = *(const uint4*)(Ks1 + 4*j);
                pwv[4*j  ] += a0*__uint_as_float(ka.x) + a1*__uint_as_float(kb.x);
                pwv[4*j+1] += a0*__uint_as_float(ka.y) + a1*__uint_as_float(kb.y);
                pwv[4*j+2] += a0*__uint_as_float(ka.z) + a1*__uint_as_float(kb.z);
                pwv[4*j+3] += a0*__uint_as_float(ka.w) + a1*__uint_as_float(kb.w);
            }
        }
        __syncthreads();
    }

    // ---- reduce o/w partials (reuse tile smem; 16 rows) ----
    float* opart = (float*)sm;
    float* wpart = (float*)(sm + TILE_U);
    #pragma unroll
    for (int j = 0; j < 8; j++) {
        opart[sn*DH + sc + j] = pov[j];
        wpart[sn*DH + sc + j] = pwv[j];
    }
    __syncthreads();
    if (tid < DH) {
        float s = 0.f;
        #pragma unroll
        for (int n = 0; n < 16; n++) s += opart[n*DH + tid];
        o_sm[tid] = s;
    } else {
        int t = tid - DH;
        float s = 0.f;
        #pragma unroll
        for (int n = 0; n < 16; n++) s += wpart[n*DH + t];
        w_sm[t] = s;
    }
    __syncthreads();

    // ---- epilogue ----
    float* ob = out + ((size_t)b*NQ + q) * DH * DH;
    #pragma unroll
    for (int mi = 0; mi < 4; mi++) {
        int vr = v0 + mi*16 + g;
        float ov1 = o_sm[vr], ov2 = o_sm[vr + 8];
        #pragma unroll
        for (int nj = 0; nj < 4; nj++) {
            int kc = k0 + nj*8 + ti*2;
            float w1 = w_sm[kc], w2 = w_sm[kc+1];
            float2 r1 = make_float2(SCALE*(acc[mi][nj][0] - ov1*w1),
                                    SCALE*(acc[mi][nj][1] - ov1*w2));
            float2 r2 = make_float2(SCALE*(acc[mi][nj][2] - ov2*w1),
                                    SCALE*(acc[mi][nj][3] - ov2*w2));
            *(float2*)(ob + (size_t)vr*DH + kc)     = r1;
            *(float2*)(ob + (size_t)(vr+8)*DH + kc) = r2;
        }
    }
}

extern "C" void kernel_launch(void* const* d_in, const int* in_sizes, int n_in,
                              void* d_out, int out_size) {
    const float* Q = (const float*)d_in[0];
    const float* K = (const float*)d_in[1];
    const float* V = (const float*)d_in[2];
    float* out = (float*)d_out;
    int batch = in_sizes[1] / (SEQ * DH);
    int total4 = batch * SEQ * DH / 4;
    prep_kernel<<<(total4 + 255)/256, 256>>>(K, V, total4);
    cudaFuncSetAttribute(jac_tc, cudaFuncAttributeMaxDynamicSharedMemorySize, DSMEM);
    jac_tc<<<dim3(NQ, batch), 256, DSMEM>>>(Q, K, out);
}